// round 6
// baseline (speedup 1.0000x reference)
#include <cuda_runtime.h>

#define NFFT 16000
#define NH   8000
#define BT   800
// forward-domain padding (16000): conflict-free for strides 800, 40, 10
#define PHI(i)  ((i) + 2 * ((i) / 40))
#define SMPAD   (NFFT + 2 * (NFFT / 40))              // 16800 float2
// inverse-domain padding (8000): strides 5, 20, 400
#define PHI8(i) ((i) + ((i) / 20) + 8 * ((i) / 400))
#define SMPAD8  (NH + NH / 20 + 8 * (NH / 400))       // 8560 float2
#define SMTOTAL ((SMPAD + SMPAD8) * sizeof(float2))   // 202,880 B

// Forward plan (DIF) on 16000: 20,20,4,10 -> strides m: 800,40,10,1
//   p = 800d0+40d1+10d2+d3 holds f = d0+20d1+400d2+1600d3
//   block b = p/10 = 80d0+4d1+d2, f0 = d0+20d1+400d2 in [0,1600)
// Inverse plan (DIT) on 8000: [5 fused, 4, 20, 20]: input p' = 5b+t for
//   C[f0+1600t]; NS sequence 5, 20, 400, 8000; output natural.

__device__ float2 g_tw[NFFT];   // e^{-2*pi*i*t/16000}

__global__ void init_tables_kernel() {
    int p = blockIdx.x * blockDim.x + threadIdx.x;
    if (p < NFFT) {
        double ang = -2.0 * 3.14159265358979323846 * (double)p / (double)NFFT;
        g_tw[p] = make_float2((float)cos(ang), (float)sin(ang));
    }
}

__device__ __forceinline__ int block_of(int f0) {
    return 80 * (f0 % 20) + 4 * ((f0 / 20) % 20) + (f0 / 400);
}

__device__ __forceinline__ float2 cadd(float2 a, float2 b) { return make_float2(a.x + b.x, a.y + b.y); }
__device__ __forceinline__ float2 csub(float2 a, float2 b) { return make_float2(a.x - b.x, a.y - b.y); }
__device__ __forceinline__ float2 cmul(float2 a, float2 b) {
    return make_float2(fmaf(a.x, b.x, -a.y * b.y), fmaf(a.x, b.y, a.y * b.x));
}
__device__ __forceinline__ float2 cmulc(float2 a, float cr, float ci) {
    return make_float2(fmaf(a.x, cr, -a.y * ci), fmaf(a.x, ci, a.y * cr));
}
template <int DIR>
__device__ __forceinline__ float2 cmuli(float2 a) {   // * (DIR*i)
    return (DIR > 0) ? make_float2(-a.y, a.x) : make_float2(a.y, -a.x);
}

template <int DIR>
__device__ __forceinline__ void dft4(float2* x) {
    float2 t0 = cadd(x[0], x[2]);
    float2 t1 = csub(x[0], x[2]);
    float2 t2 = cadd(x[1], x[3]);
    float2 t3 = cmuli<DIR>(csub(x[1], x[3]));
    x[0] = cadd(t0, t2);
    x[2] = csub(t0, t2);
    x[1] = cadd(t1, t3);
    x[3] = csub(t1, t3);
}

template <int DIR>
__device__ __forceinline__ void dft5(float2* x) {
    const float c1 = 0.30901699437494742f;
    const float c2 = -0.80901699437494745f;
    const float s1 = 0.95105651629515357f;
    const float s2 = 0.58778525229247313f;
    float2 t1 = cadd(x[1], x[4]);
    float2 t2 = cadd(x[2], x[3]);
    float2 t3 = csub(x[1], x[4]);
    float2 t4 = csub(x[2], x[3]);
    float2 x0 = x[0];
    float2 a1 = make_float2(x0.x + c1 * t1.x + c2 * t2.x, x0.y + c1 * t1.y + c2 * t2.y);
    float2 a2 = make_float2(x0.x + c2 * t1.x + c1 * t2.x, x0.y + c2 * t1.y + c1 * t2.y);
    float2 b1 = make_float2(s1 * t3.x + s2 * t4.x, s1 * t3.y + s2 * t4.y);
    float2 b2 = make_float2(s2 * t3.x - s1 * t4.x, s2 * t3.y - s1 * t4.y);
    x[0] = make_float2(x0.x + t1.x + t2.x, x0.y + t1.y + t2.y);
    float2 ib1 = cmuli<DIR>(b1);
    float2 ib2 = cmuli<DIR>(b2);
    x[1] = cadd(a1, ib1);
    x[4] = csub(a1, ib1);
    x[2] = cadd(a2, ib2);
    x[3] = csub(a2, ib2);
}

// 10-point DFT = 2x5 CT (used in the fused middle), unit stride.
template <int DIR>
__device__ __forceinline__ void dft10(float2* x) {
    const float C36 = 0.80901699437494742f;
    const float S36 = 0.58778525229247313f;
    const float C72 = 0.30901699437494742f;
    const float S72 = 0.95105651629515357f;
    const float D = (float)DIR;
    float2 a[5], c[5];
#pragma unroll
    for (int k = 0; k < 5; k++) {
        a[k] = cadd(x[k], x[k + 5]);
        c[k] = csub(x[k], x[k + 5]);
    }
    c[1] = cmulc(c[1], C36, D * S36);
    c[2] = cmulc(c[2], C72, D * S72);
    c[3] = cmulc(c[3], -C72, D * S72);
    c[4] = cmulc(c[4], -C36, D * S36);
    dft5<DIR>(a);
    dft5<DIR>(c);
    x[0] = a[0]; x[2] = a[1]; x[4] = a[2]; x[6] = a[3]; x[8] = a[4];
    x[1] = c[0]; x[3] = c[1]; x[5] = c[2]; x[7] = c[3]; x[9] = c[4];
}

// 20-point DFT = 4x5 CT in registers. n = 5a+b, k = c+4d.
template <int DIR>
__device__ __forceinline__ void dft20(float2* x) {
    const float c18 = 0.95105651629515357f, s18 = 0.30901699437494742f;
    const float c36 = 0.80901699437494742f, s36 = 0.58778525229247313f;
    const float D = (float)DIR;
    float2 Y[20];   // Y[c*5 + b]
#pragma unroll
    for (int b = 0; b < 5; b++) {
        float2 t[4] = {x[b], x[b + 5], x[b + 10], x[b + 15]};
        dft4<DIR>(t);
        if (b == 1) {
            t[1] = cmulc(t[1], c18, D * s18);   // 18 deg
            t[2] = cmulc(t[2], c36, D * s36);   // 36
            t[3] = cmulc(t[3], s36, D * c36);   // 54
        } else if (b == 2) {
            t[1] = cmulc(t[1], c36, D * s36);   // 36
            t[2] = cmulc(t[2], s18, D * c18);   // 72
            t[3] = cmulc(t[3], -s18, D * c18);  // 108
        } else if (b == 3) {
            t[1] = cmulc(t[1], s36, D * c36);   // 54
            t[2] = cmulc(t[2], -s18, D * c18);  // 108
            t[3] = cmulc(t[3], -c18, D * s18);  // 162
        } else if (b == 4) {
            t[1] = cmulc(t[1], s18, D * c18);   // 72
            t[2] = cmulc(t[2], -c36, D * s36);  // 144
            t[3] = cmulc(t[3], -c36, -D * s36); // 216
        }
        Y[0 + b] = t[0]; Y[5 + b] = t[1]; Y[10 + b] = t[2]; Y[15 + b] = t[3];
    }
#pragma unroll
    for (int c = 0; c < 4; c++) {
        float2 u[5] = {Y[c * 5], Y[c * 5 + 1], Y[c * 5 + 2], Y[c * 5 + 3], Y[c * 5 + 4]};
        dft5<DIR>(u);
        x[c] = u[0]; x[c + 4] = u[1]; x[c + 8] = u[2]; x[c + 12] = u[3]; x[c + 16] = u[4];
    }
}

// Load w^1,w^2,w^3,w^4,w^8,w^12,w^16 directly from the table (all indices < 16000).
template <bool CJ>
__device__ __forceinline__ void tw20_load(int t, float2* w) {
    w[0] = g_tw[t];      w[1] = g_tw[2 * t];  w[2] = g_tw[3 * t];
    w[3] = g_tw[4 * t];  w[4] = g_tw[8 * t];  w[5] = g_tw[12 * t];
    w[6] = g_tw[16 * t];
    if (CJ) {
#pragma unroll
        for (int k = 0; k < 7; k++) w[k].y = -w[k].y;
    }
}

__device__ __forceinline__ void apply_tw20(float2* x, const float2* w) {
    x[1]  = cmul(x[1],  w[0]);
    x[2]  = cmul(x[2],  w[1]);
    x[3]  = cmul(x[3],  w[2]);
    x[4]  = cmul(x[4],  w[3]);
    x[5]  = cmul(cmul(x[5],  w[3]), w[0]);
    x[6]  = cmul(cmul(x[6],  w[3]), w[1]);
    x[7]  = cmul(cmul(x[7],  w[3]), w[2]);
    x[8]  = cmul(x[8],  w[4]);
    x[9]  = cmul(cmul(x[9],  w[4]), w[0]);
    x[10] = cmul(cmul(x[10], w[4]), w[1]);
    x[11] = cmul(cmul(x[11], w[4]), w[2]);
    x[12] = cmul(x[12], w[5]);
    x[13] = cmul(cmul(x[13], w[5]), w[0]);
    x[14] = cmul(cmul(x[14], w[5]), w[1]);
    x[15] = cmul(cmul(x[15], w[5]), w[2]);
    x[16] = cmul(x[16], w[6]);
    x[17] = cmul(cmul(x[17], w[6]), w[0]);
    x[18] = cmul(cmul(x[18], w[6]), w[1]);
    x[19] = cmul(cmul(x[19], w[6]), w[2]);
}

// ---------------- forward stages (16000 domain, DIF) ----------------

// radix-20, NS in {16000, 800}; exactly 800 tasks = 1/thread.
// PHI(base + j*m) = PHI(base) + j*(m + 2*(m/40))  [m % 40 == 0]
template <int NS>
__device__ __forceinline__ void fwd_stage20(float2* sm, int tid) {
    constexpr int m = NS / 20;
    constexpr int K = NFFT / NS;
    constexpr int PS = m + 2 * (m / 40);
    int blk = tid / m;
    int n2 = tid - blk * m;
    int pb = PHI(blk * NS + n2);
    float2 x[20];
#pragma unroll
    for (int j = 0; j < 20; j++) x[j] = sm[pb + j * PS];
    dft20<-1>(x);
    float2 w[7];
    tw20_load<false>(n2 * K, w);
    apply_tw20(x, w);
#pragma unroll
    for (int j = 0; j < 20; j++) sm[pb + j * PS] = x[j];
}

// radix-4, NS=40, m=10: 4000 tasks = exactly 5/thread.
// base = 40*blk + n2 (n2<10), offsets n2+10j <= 39 stay in one 40-group -> PS=10.
__device__ __forceinline__ void fwd_stage4(float2* sm, int tid) {
#pragma unroll
    for (int it = 0; it < 5; it++) {
        int u = tid + it * BT;
        int blk = u / 10;
        int n2 = u - 10 * blk;
        int pb = PHI(40 * blk + n2);
        float2 x[4];
#pragma unroll
        for (int j = 0; j < 4; j++) x[j] = sm[pb + 10 * j];
        dft4<-1>(x);
        float2 w1 = g_tw[n2 * 400];
        float2 w2 = g_tw[n2 * 800];
        float2 w3 = g_tw[n2 * 1200];
        x[1] = cmul(x[1], w1);
        x[2] = cmul(x[2], w2);
        x[3] = cmul(x[3], w3);
#pragma unroll
        for (int j = 0; j < 4; j++) sm[pb + 10 * j] = x[j];
    }
}

// ---------------- inverse stages (8000 domain, DIT) ----------------

// radix-4, NS=20, m=5: 2000 tasks (2.5/thread, light).
__device__ __forceinline__ void inv_stage4(float2* s8, int tid) {
    for (int u = tid; u < 2000; u += BT) {
        int blk = u / 5;
        int n2 = u - 5 * blk;
        int pb = PHI8(20 * blk + n2);   // n2+5j <= 19: stays in one 20-group
        float2 x[4];
#pragma unroll
        for (int j = 0; j < 4; j++) x[j] = s8[pb + 5 * j];
        float2 w1 = g_tw[n2 * 800];  w1.y = -w1.y;
        float2 w2 = g_tw[n2 * 1600]; w2.y = -w2.y;
        float2 w3 = g_tw[n2 * 2400]; w3.y = -w3.y;
        x[1] = cmul(x[1], w1);
        x[2] = cmul(x[2], w2);
        x[3] = cmul(x[3], w3);
        dft4<1>(x);
#pragma unroll
        for (int j = 0; j < 4; j++) s8[pb + 5 * j] = x[j];
    }
}

// radix-20, NS in {400, 8000}: 400 tasks, threads >= 400 idle.
// NS=400: PS = 20 + 1 = 21 ; NS=8000: PS = 400 + 20 + 8 = 428 (exact affine).
template <int NS, bool TO_GMEM>
__device__ __forceinline__ void inv_stage20(float2* s8, int tid, float2* __restrict__ gout2) {
    constexpr int m = NS / 20;
    constexpr int K2 = NFFT / NS;
    constexpr int PS = m + m / 20 + 8 * (m / 400);
    if (tid >= 400) return;
    int blk = tid / m;
    int n2 = tid - blk * m;
    int base = blk * NS + n2;
    int pb = PHI8(base);
    float2 x[20];
#pragma unroll
    for (int j = 0; j < 20; j++) x[j] = s8[pb + j * PS];
    float2 w[7];
    tw20_load<true>(n2 * K2, w);
    apply_tw20(x, w);
    dft20<1>(x);
#pragma unroll
    for (int j = 0; j < 20; j++) {
        if constexpr (TO_GMEM) gout2[base + j * m] = x[j];   // c[n] -> (z[2n], z[2n+1])
        else s8[pb + j * PS] = x[j];
    }
}

// ---------------- fused middle ----------------

__device__ __forceinline__ void pw(float2& A, float2& C, float scale) {
    float2 a = A, c = C;
    float2 Fi = make_float2(a.x + c.x, a.y - c.y);
    float2 Fs = make_float2(a.y + c.y, -(a.x - c.x));
    float2 Z = cmul(Fi, Fs);
    Z.x *= scale; Z.y *= scale;
    A = Z;
    C = make_float2(Z.x, -Z.y);
}

// Pack 10 Z-values (f = f0+1600t) into 5 C-values (8000 domain), then inverse
// radix-5 (m=1); store at s8[PHI8(5b)+j] (5 contiguous, never cross a 20-group).
__device__ __forceinline__ void pack_inv5_store(const float2* x, float2 w0,
                                                float2* s8, int b) {
    const float RC[5] = {1.f, 0.80901699437494742f, 0.30901699437494742f,
                         -0.30901699437494742f, -0.80901699437494742f};
    const float RS[5] = {0.f, 0.58778525229247313f, 0.95105651629515357f,
                         0.95105651629515357f, 0.58778525229247313f};
    float2 C[5];
#pragma unroll
    for (int t = 0; t < 5; t++) {
        float2 S = cadd(x[t], x[t + 5]);
        float2 Dd = csub(x[t], x[t + 5]);
        float2 wt = (t == 0) ? w0 : cmul(w0, make_float2(RC[t], RS[t]));
        C[t] = cadd(S, cmuli<1>(cmul(wt, Dd)));
    }
    dft5<1>(C);
    int base = PHI8(5 * b);
#pragma unroll
    for (int j = 0; j < 5; j++) s8[base + j] = C[j];
}

// forward radix-10 (m=1) + Hermitian pointwise + pack + inverse radix-5, in regs.
__device__ __forceinline__ void fused_mid(float2* sm, float2* s8, int tid) {
    const float scale = 0.25f / (float)NFFT;
    int fa, fb;
    if (tid < 799) { fa = tid + 1; fb = 1600 - fa; }
    else           { fa = 0;       fb = 800; }
    int b  = block_of(fa);
    int b2 = block_of(fb);
    int pa = PHI(10 * b);    // 10-block never crosses a 40-group (10b%40<=30)
    int pb = PHI(10 * b2);
    float2 xa[10], xb[10];
#pragma unroll
    for (int k = 0; k < 5; k++) {
        float4 t = *(const float4*)&sm[pa + 2 * k];
        xa[2 * k] = make_float2(t.x, t.y); xa[2 * k + 1] = make_float2(t.z, t.w);
        float4 s = *(const float4*)&sm[pb + 2 * k];
        xb[2 * k] = make_float2(s.x, s.y); xb[2 * k + 1] = make_float2(s.z, s.w);
    }
    dft10<-1>(xa);
    dft10<-1>(xb);
    if (tid < 799) {
#pragma unroll
        for (int t = 0; t < 10; t++) pw(xa[t], xb[9 - t], scale);
    } else {
        pw(xa[0], xa[0], scale);
        pw(xa[5], xa[5], scale);
        pw(xa[1], xa[9], scale);
        pw(xa[2], xa[8], scale);
        pw(xa[3], xa[7], scale);
        pw(xa[4], xa[6], scale);
        pw(xb[0], xb[9], scale);
        pw(xb[1], xb[8], scale);
        pw(xb[2], xb[7], scale);
        pw(xb[3], xb[6], scale);
        pw(xb[4], xb[5], scale);
    }
    float2 ta = g_tw[fa]; ta.y = -ta.y;   // e^{+2pi i fa/16000}
    float2 tb = g_tw[fb]; tb.y = -tb.y;
    pack_inv5_store(xa, ta, s8, b);
    pack_inv5_store(xb, tb, s8, b2);
}

// ---------------- main kernel ----------------

__global__ void __launch_bounds__(BT) mcb_main_kernel(
    const float* __restrict__ img, const float* __restrict__ seq,
    const int* __restrict__ hv, const float* __restrict__ sv,
    float* __restrict__ out, int d) {
    extern __shared__ float2 sm[];
    float2* s8 = sm + SMPAD;
    const int b = blockIdx.x;
    const int tid = threadIdx.x;

    float4* sm4 = (float4*)sm;
    for (int i = tid; i < SMPAD / 2; i += BT) sm4[i] = make_float4(0.f, 0.f, 0.f, 0.f);
    __syncthreads();

    const float* irow = img + (size_t)b * d;
    const float* qrow = seq + (size_t)b * d;
    for (int i = tid; i < d; i += BT) {
        int h = PHI(hv[i]);
        float s = sv[i];
        atomicAdd(&sm[h].x, irow[i] * s);
        atomicAdd(&sm[h].y, qrow[i] * s);
    }
    __syncthreads();

    float2* orow2 = (float2*)(out + (size_t)b * NFFT);

    // forward: 20 (m=800), 20 (m=40), 4 (m=10) | fused(10 + pw + pack + inv5)
    fwd_stage20<16000>(sm, tid);  __syncthreads();
    fwd_stage20<800>(sm, tid);    __syncthreads();
    fwd_stage4(sm, tid);          __syncthreads();
    fused_mid(sm, s8, tid);       __syncthreads();
    // inverse 8000: 4 (m=5), 20 (m=20), 20 (m=400) -> gmem
    inv_stage4(s8, tid);                    __syncthreads();
    inv_stage20<400, false>(s8, tid, orow2);  __syncthreads();
    inv_stage20<8000, true>(s8, tid, orow2);
}

extern "C" void kernel_launch(void* const* d_in, const int* in_sizes, int n_in,
                              void* d_out, int out_size) {
    const float* img = (const float*)d_in[0];
    const float* seq = (const float*)d_in[1];
    const int* hv = (const int*)d_in[2];
    const float* sv = (const float*)d_in[3];
    float* out = (float*)d_out;

    int d = in_sizes[2];
    int B = in_sizes[0] / d;

    static_assert(NFFT == 16000 && NH == 8000, "plan assumes N=16000");

    cudaFuncSetAttribute(mcb_main_kernel, cudaFuncAttributeMaxDynamicSharedMemorySize,
                         SMTOTAL);

    init_tables_kernel<<<(NFFT + 255) / 256, 256>>>();
    mcb_main_kernel<<<B, BT, SMTOTAL>>>(img, seq, hv, sv, out, d);
}